// round 12
// baseline (speedup 1.0000x reference)
#include <cuda_runtime.h>
#include <cstdint>

// B=4, H=512, W=512, K=8, BKG_DEPTH=100
// Inputs: colors f32[B,H,W,8,4], zbuf f32[B,H,W,8], labels i32[B,H,W,8], bg f32[3]
// Output (flat f32): image[NPIX*4] | depth[NPIX] | label[NPIX] | human[NPIX*8*4]

constexpr int   NPIX      = 4 * 512 * 512;     // 1,048,576
constexpr float BKG_DEPTH = 100.0f;

constexpr long long IMG_OFF   = 0;
constexpr long long DEPTH_OFF = (long long)NPIX * 4;
constexpr long long LABEL_OFF = DEPTH_OFF + NPIX;
constexpr long long HUMAN_OFF = LABEL_OFF + NPIX;

constexpr int BLOCK = 128;                     // threads == pixels per tile
constexpr int GRID  = NPIX / BLOCK / 2;        // 4096 CTAs, 2 tiles each

// ---- Blackwell 256-bit global access helpers (sm_100+/103a) ----
__device__ __forceinline__ void ldg256_u(const void* p, uint32_t* v) {
    asm volatile("ld.global.nc.v8.b32 {%0,%1,%2,%3,%4,%5,%6,%7}, [%8];"
        : "=r"(v[0]), "=r"(v[1]), "=r"(v[2]), "=r"(v[3]),
          "=r"(v[4]), "=r"(v[5]), "=r"(v[6]), "=r"(v[7])
        : "l"(p));
}
__device__ __forceinline__ void stg256_cs(void* p, float4 a, float4 b) {
    asm volatile("st.global.cs.v8.b32 [%0], {%1,%2,%3,%4,%5,%6,%7,%8};"
        :: "l"(p),
           "r"(__float_as_uint(a.x)), "r"(__float_as_uint(a.y)),
           "r"(__float_as_uint(a.z)), "r"(__float_as_uint(a.w)),
           "r"(__float_as_uint(b.x)), "r"(__float_as_uint(b.y)),
           "r"(__float_as_uint(b.z)), "r"(__float_as_uint(b.w))
        : "memory");
}

__global__ void __launch_bounds__(BLOCK, 6)    // smem-capped at 6 CTAs/SM anyway
alpha_composite_kernel(const float4* __restrict__ colors,   // [NPIX*8] float4
                       const float*  __restrict__ zbuf,     // [NPIX*8]
                       const int*    __restrict__ labl,     // [NPIX*8]
                       const float*  __restrict__ bg,       // [3]
                       float*        __restrict__ out)
{
    // Two 16 KB XOR-swizzled tile buffers: slot(q,j) = q*8 + (j^(q&7)).
    __shared__ float4 sbufA[BLOCK * 8];
    __shared__ float4 sbufB[BLOCK * 8];
    __shared__ unsigned stab[BLOCK];   // nibble n = first layer k w/ label n (0xF=miss)

    const int tid = threadIdx.x;
    const long long t0 = (long long)blockIdx.x * 2;     // first of two tiles
    const long long t1 = t0 + 1;

    auto prefetch = [&](long long t, float4* buf) {
        const long long fbase = t * BLOCK * 8;          // float4 units
#pragma unroll
        for (int it = 0; it < 8; ++it) {
            const int idx = it * BLOCK + tid;           // coalesced
            const int q = idx >> 3, j = idx & 7;
            const uint32_t saddr =
                (uint32_t)__cvta_generic_to_shared(&buf[q * 8 + (j ^ (q & 7))]);
            const float4* g = colors + fbase + idx;
            asm volatile("cp.async.cg.shared.global [%0], [%1], 16;\n"
                         :: "r"(saddr), "l"(g));
        }
        asm volatile("cp.async.commit_group;\n");
    };

    // ---- stage both tiles' colors; z/labels via 256-bit loads ----
    prefetch(t0, sbufA);
    prefetch(t1, sbufB);

    uint32_t zu0[8], zu1[8], lu0[8], lu1[8];
    {
        const long long p0 = t0 * BLOCK + tid;
        const long long p1 = t1 * BLOCK + tid;
        ldg256_u(zbuf + p0 * 8, zu0);
        ldg256_u(zbuf + p1 * 8, zu1);
        ldg256_u(labl + p0 * 8, lu0);
        ldg256_u(labl + p1 * 8, lu1);
    }
    const float bgr = __ldg(bg + 0);
    const float bgg = __ldg(bg + 1);
    const float bgb = __ldg(bg + 2);

    auto pack_labels = [](const uint32_t* lu) -> unsigned {
        unsigned L = 0;
#pragma unroll
        for (int k = 0; k < 8; ++k) L |= (lu[k] & 7u) << (4 * k);
        return L;
    };

    // ---- process one tile: fused scan + in-place blend, then v8 drain ----
    auto process = [&](long long t, float4* buf,
                       const uint32_t* zu, unsigned Lpack) {
        const long long p     = t * BLOCK + tid;
        const long long fbase = t * BLOCK * 8;          // float4 units

        float r = bgr, g = bgg, b = bgb;
        float a = 0.0f;
        float d = BKG_DEPTH;
        float labv = -1.0f;          // miss sentinel -> output -1 directly
        unsigned T = 0xFFFFFFFFu;    // 8 nibbles, 0xF = miss

#pragma unroll
        for (int k = 7; k >= 0; --k) {
            const int slot = tid * 8 + (k ^ (tid & 7));
            const float4 c = buf[slot];
            const float zk = __uint_as_float(zu[k]);
            const float al = c.w;
            const float om = 1.0f - al;
            const unsigned lk = (Lpack >> (4 * k)) & 7u;

            r = c.x * al + r * om;
            g = c.y * al + g * om;
            b = c.z * al + b * om;
            a = fmaxf(al, a);

            const bool znn = !(zk < 0.0f);          // reference NaN handling
            if (zk > 0.0f)        d    = zk * al + d * om;
            if (znn && al > 0.5f) labv = (float)lk;

            buf[slot] = make_float4(c.x * al + bgr * om,   // human blend in-place
                                    c.y * al + bgg * om,
                                    c.z * al + bgb * om,
                                    al);

            if (znn)                                 // descending k: first k wins
                T = (T & ~(0xFu << (4 * lk))) | ((unsigned)k << (4 * lk));
        }
        stab[tid] = T;

        reinterpret_cast<float4*>(out + IMG_OFF)[p] = make_float4(r, g, b, a);
        out[DEPTH_OFF + p] = d;
        out[LABEL_OFF + p] = labv;

        __syncthreads();

        // drain: 32 B per thread per iter, streaming stores
        float4* ho = reinterpret_cast<float4*>(out + HUMAN_OFF);
#pragma unroll
        for (int it = 0; it < 4; ++it) {
            const int idx2 = it * BLOCK + tid;       // pair index, coalesced
            const int q  = idx2 >> 2;                // pixel within tile
            const int n0 = (idx2 & 3) * 2;           // labels n0, n0+1
            const unsigned Tq = stab[q];
            const unsigned k0 = (Tq >> (4 * n0)) & 0xFu;
            const unsigned k1 = (Tq >> (4 * n0 + 4)) & 0xFu;
            const float4 miss = make_float4(bgr, bgg, bgb, 0.0f);
            const float4 v0 = (k0 < 8u) ? buf[q * 8 + ((int)k0 ^ (q & 7))] : miss;
            const float4 v1 = (k1 < 8u) ? buf[q * 8 + ((int)k1 ^ (q & 7))] : miss;
            stg256_cs(ho + fbase + 2 * idx2, v0, v1);
        }
    };

    // tile 0: its cp.async group is the older of the two pending
    asm volatile("cp.async.wait_group 1;\n");
    __syncthreads();
    process(t0, sbufA, zu0, pack_labels(lu0));

    // tile 1 (barrier also orders stab reuse)
    asm volatile("cp.async.wait_group 0;\n");
    __syncthreads();
    process(t1, sbufB, zu1, pack_labels(lu1));
}

extern "C" void kernel_launch(void* const* d_in, const int* in_sizes, int n_in,
                              void* d_out, int out_size)
{
    const float4* colors = (const float4*)d_in[0];
    const float*  zbuf   = (const float*)d_in[1];
    const int*    labl   = (const int*)d_in[2];
    const float*  bg     = (const float*)d_in[3];
    float*        out    = (float*)d_out;

    alpha_composite_kernel<<<GRID, BLOCK>>>(colors, zbuf, labl, bg, out);
}

// round 13
// speedup vs baseline: 1.0033x; 1.0033x over previous
#include <cuda_runtime.h>
#include <cstdint>

// B=4, H=512, W=512, K=8, BKG_DEPTH=100
// Inputs: colors f32[B,H,W,8,4], zbuf f32[B,H,W,8], labels i32[B,H,W,8], bg f32[3]
// Output (flat f32): image[NPIX*4] | depth[NPIX] | label[NPIX] | human[NPIX*8*4]

constexpr int   NPIX      = 4 * 512 * 512;     // 1,048,576
constexpr float BKG_DEPTH = 100.0f;

constexpr long long IMG_OFF   = 0;
constexpr long long DEPTH_OFF = (long long)NPIX * 4;
constexpr long long LABEL_OFF = DEPTH_OFF + NPIX;
constexpr long long HUMAN_OFF = LABEL_OFF + NPIX;

constexpr int BLOCK = 128;                     // threads == pixels per tile

// Streaming (evict-first) stores: keep the single-use 152 MiB write stream
// out of L2 so input reads stay resident across harness graph replays.
__device__ __forceinline__ void stg_cs_v4(void* p, float4 v) {
    asm volatile("st.global.cs.v4.f32 [%0], {%1,%2,%3,%4};"
        :: "l"(p), "f"(v.x), "f"(v.y), "f"(v.z), "f"(v.w) : "memory");
}
__device__ __forceinline__ void stg_cs_f32(void* p, float v) {
    asm volatile("st.global.cs.f32 [%0], %1;" :: "l"(p), "f"(v) : "memory");
}

__global__ void __launch_bounds__(BLOCK, 10)   // reg cap 51 (R11 measured 48)
alpha_composite_kernel(const float4* __restrict__ colors,   // [NPIX*8] float4
                       const float4* __restrict__ zbuf4,    // [NPIX*2] float4
                       const int4*   __restrict__ labl4,    // [NPIX*2] int4
                       const float*  __restrict__ bg,       // [3]
                       float*        __restrict__ out)
{
    // 16 KB staging buffer, XOR-swizzled: slot(q,j) = q*8 + (j^(q&7)).
    // Conflict-free for both coalesced fill/drain and per-pixel strided access.
    __shared__ float4 sbuf[BLOCK * 8];
    // Per-pixel nibble table: nibble n = first layer k with label n (0xF = miss)
    __shared__ unsigned stab[BLOCK];

    const int tid = threadIdx.x;
    const long long p     = (long long)blockIdx.x * BLOCK + tid;
    const long long fbase = (long long)blockIdx.x * BLOCK * 8;   // float4 units

    // ---- Phase 1: cp.async color fill (no register staging, L2-streaming) ----
#pragma unroll
    for (int it = 0; it < 8; ++it) {
        const int idx = it * BLOCK + tid;              // coalesced
        const int q = idx >> 3, j = idx & 7;
        const uint32_t saddr =
            (uint32_t)__cvta_generic_to_shared(&sbuf[q * 8 + (j ^ (q & 7))]);
        const float4* gptr = colors + fbase + idx;
        asm volatile("cp.async.cg.shared.global [%0], [%1], 16;\n"
                     :: "r"(saddr), "l"(gptr));
    }
    asm volatile("cp.async.commit_group;\n");

    // Overlap: z / labels / bg loads while cp.async is in flight
    const float4 z0 = zbuf4[p * 2 + 0];
    const float4 z1 = zbuf4[p * 2 + 1];
    const int4   l0 = labl4[p * 2 + 0];
    const int4   l1 = labl4[p * 2 + 1];
    const float bgr = __ldg(bg + 0);
    const float bgg = __ldg(bg + 1);
    const float bgb = __ldg(bg + 2);

    const float zz[8] = { z0.x, z0.y, z0.z, z0.w, z1.x, z1.y, z1.z, z1.w };
    // Pack 8 labels (each in [0,8)) into one nibble word: saves 7 live regs.
    const unsigned Lpack =
        ((unsigned)l0.x      ) | ((unsigned)l0.y <<  4) |
        ((unsigned)l0.z <<  8) | ((unsigned)l0.w << 12) |
        ((unsigned)l1.x << 16) | ((unsigned)l1.y << 20) |
        ((unsigned)l1.z << 24) | ((unsigned)l1.w << 28);

    asm volatile("cp.async.wait_group 0;\n");
    __syncthreads();

    // ---- Phase 2: fused back-to-front scan + human blend (in-place) ----
    float r = bgr, g = bgg, b = bgb;
    float a = 0.0f;
    float d = BKG_DEPTH;
    float labv = -1.0f;          // miss sentinel -> output -1 directly
    unsigned T = 0xFFFFFFFFu;    // 8 nibbles, 0xF = miss

#pragma unroll
    for (int k = 7; k >= 0; --k) {
        const int slot = tid * 8 + (k ^ (tid & 7));
        const float4 c = sbuf[slot];
        const float al = c.w;
        const float om = 1.0f - al;
        const unsigned lk = (Lpack >> (4 * k)) & 7u;

        r = c.x * al + r * om;
        g = c.y * al + g * om;
        b = c.z * al + b * om;
        a = fmaxf(al, a);

        const bool znn = !(zz[k] < 0.0f);          // reference NaN handling
        if (zz[k] > 0.0f)     d    = zz[k] * al + d * om;
        if (znn && al > 0.5f) labv = (float)lk;

        // human blend overwrites the color slot (this thread is sole owner)
        sbuf[slot] = make_float4(c.x * al + bgr * om,
                                 c.y * al + bgg * om,
                                 c.z * al + bgb * om,
                                 al);

        if (znn)                                    // descending k: first k wins
            T = (T & ~(0xFu << (4 * lk))) | ((unsigned)k << (4 * lk));
    }
    stab[tid] = T;

    stg_cs_v4(reinterpret_cast<float4*>(out + IMG_OFF) + p, make_float4(r, g, b, a));
    stg_cs_f32(out + DEPTH_OFF + p, d);
    stg_cs_f32(out + LABEL_OFF + p, labv);

    __syncthreads();

    // ---- Phase 3: coalesced drain of human images via nibble-table gather ----
    {
        float4* ho = reinterpret_cast<float4*>(out + HUMAN_OFF);
#pragma unroll
        for (int it = 0; it < 8; ++it) {
            const int idx = it * BLOCK + tid;              // coalesced
            const int q = idx >> 3, n = idx & 7;           // pixel q, label n
            const unsigned kk = (stab[q] >> (4 * n)) & 0xFu;
            float4 v;
            if (kk < 8u) v = sbuf[q * 8 + ((int)kk ^ (q & 7))];
            else         v = make_float4(bgr, bgg, bgb, 0.0f);  // miss -> (bg,0)
            stg_cs_v4(ho + fbase + idx, v);
        }
    }
}

extern "C" void kernel_launch(void* const* d_in, const int* in_sizes, int n_in,
                              void* d_out, int out_size)
{
    const float4* colors = (const float4*)d_in[0];
    const float4* zbuf4  = (const float4*)d_in[1];
    const int4*   labl4  = (const int4*)d_in[2];
    const float*  bg     = (const float*)d_in[3];
    float*        out    = (float*)d_out;

    alpha_composite_kernel<<<NPIX / BLOCK, BLOCK>>>(colors, zbuf4, labl4, bg, out);
}